// round 17
// baseline (speedup 1.0000x reference)
#include <cuda_runtime.h>
#include <cuda_fp16.h>
#include <cstdint>
#include <math.h>

#define BB 4
#define NB 288
#define NC 32
#define NP 16
#define HW 196
#define EPSF 1e-5f

#define NVPHW (BB*NC*NP*HW)   // 401408
#define NCHW  (BB*NC*HW)      // 25088
#define NCHW4 (NCHW/4)        // 6272

// scratch (allocation-free: __device__ globals)
__device__ float    g_s[NVPHW];
__device__ float    g_v[NVPHW];
__device__ unsigned g_maxb[NCHW];
__device__ unsigned g_minb[NCHW];
__device__ float    g_inv[NCHW];
// fp16 repack of raw u in route-optimal order:
// index = (((b*NB+B)*7 + hq)*NP + p)*224 + c*7 + q4   (uint2 = 4 hw as half2x2)
__device__ uint2    g_u16[(size_t)BB*NB*7*NP*224];    // 231 MB

// ---------------------------------------------------------------------------
__global__ void k_init() {
    int i = blockIdx.x * blockDim.x + threadIdx.x;
    if (i < NCHW) { g_maxb[i] = 0u; g_minb[i] = 0x7F800000u; }
    if (i < NVPHW) g_s[i] = 0.0f;
}

// ---------------------------------------------------------------------------
// Pass A: pose norms -> max/min over B; s0_raw = sum_B u; ALSO emits the
// fp16 repack of raw u (route passes read only the repack, fully coalesced).
// grid (9 Bgroups of 32, 4 c-groups of 8, 4 b), 392 threads = (csub, q4g)
__global__ void __launch_bounds__(392, 1) k_passA(const float* __restrict__ u) {
    int bg = blockIdx.x;          // 0..8
    int cg = blockIdx.y;          // 0..3
    int b  = blockIdx.z;          // 0..3
    int tid = threadIdx.x;
    int csub = tid / 49;          // 0..7
    int q4g  = tid % 49;          // 0..48
    int c = cg * 8 + csub;
    int hwoff = q4g * 4;
    int hq  = q4g / 7;            // 0..6
    int q4l = q4g % 7;            // 0..6

    float4 sacc[NP];
#pragma unroll
    for (int p = 0; p < NP; p++) sacc[p] = make_float4(0.f, 0.f, 0.f, 0.f);
    float4 mx = make_float4(-1e30f, -1e30f, -1e30f, -1e30f);
    float4 mn = make_float4( 1e30f,  1e30f,  1e30f,  1e30f);

    for (int bi = 0; bi < 32; bi++) {
        int Bidx = bg * 32 + bi;
        const float* up = u + (((size_t)(b * NB + Bidx) * NC + c) * NP) * HW + hwoff;
        size_t dbase = (((size_t)(b * NB + Bidx) * 7 + hq) * NP) * 224 + c * 7 + q4l;
        float4 n2 = make_float4(EPSF, EPSF, EPSF, EPSF);
#pragma unroll
        for (int p = 0; p < NP; p++) {
            float4 x = *(const float4*)(up + p * HW);
            sacc[p].x += x.x; sacc[p].y += x.y; sacc[p].z += x.z; sacc[p].w += x.w;
            n2.x += x.x * x.x; n2.y += x.y * x.y; n2.z += x.z * x.z; n2.w += x.w * x.w;
            // fp16 repack (raw u)
            __half2 h01 = __floats2half2_rn(x.x, x.y);
            __half2 h23 = __floats2half2_rn(x.z, x.w);
            uint2 pk;
            pk.x = *(unsigned*)&h01;
            pk.y = *(unsigned*)&h23;
            g_u16[dbase + (size_t)p * 224] = pk;
        }
        float4 nb = make_float4(sqrtf(n2.x), sqrtf(n2.y), sqrtf(n2.z), sqrtf(n2.w));
        mx.x = fmaxf(mx.x, nb.x); mx.y = fmaxf(mx.y, nb.y);
        mx.z = fmaxf(mx.z, nb.z); mx.w = fmaxf(mx.w, nb.w);
        mn.x = fminf(mn.x, nb.x); mn.y = fminf(mn.y, nb.y);
        mn.z = fminf(mn.z, nb.z); mn.w = fminf(mn.w, nb.w);
    }

    int mi = (b * NC + c) * HW + hwoff;
    atomicMax(&g_maxb[mi + 0], __float_as_uint(mx.x));
    atomicMax(&g_maxb[mi + 1], __float_as_uint(mx.y));
    atomicMax(&g_maxb[mi + 2], __float_as_uint(mx.z));
    atomicMax(&g_maxb[mi + 3], __float_as_uint(mx.w));
    atomicMin(&g_minb[mi + 0], __float_as_uint(mn.x));
    atomicMin(&g_minb[mi + 1], __float_as_uint(mn.y));
    atomicMin(&g_minb[mi + 2], __float_as_uint(mn.z));
    atomicMin(&g_minb[mi + 3], __float_as_uint(mn.w));

    int sbase = ((b * NC + c) * NP) * HW + hwoff;
#pragma unroll
    for (int p = 0; p < NP; p++) {
        atomicAdd(&g_s[sbase + p * HW + 0], sacc[p].x);
        atomicAdd(&g_s[sbase + p * HW + 1], sacc[p].y);
        atomicAdd(&g_s[sbase + p * HW + 2], sacc[p].z);
        atomicAdd(&g_s[sbase + p * HW + 3], sacc[p].w);
    }
}

// ---------------------------------------------------------------------------
// squash (unchanged)
__global__ void k_squash(float* __restrict__ vout, float* __restrict__ aout, int mode) {
    int i = blockIdx.x * blockDim.x + threadIdx.x;
    if (i >= NCHW4) return;
    int bc = i / 49, q4 = i % 49;
    int mi = bc * HW + q4 * 4;

    float inv[4];
    if (mode == 0) {
#pragma unroll
        for (int j = 0; j < 4; j++) {
            float mxv = __uint_as_float(g_maxb[mi + j]);
            float mnv = __uint_as_float(g_minb[mi + j]);
            inv[j] = 1.0f / (mxv - mnv);
            g_inv[mi + j] = inv[j];
        }
    } else {
        float4 iv = *(const float4*)&g_inv[mi];
        inv[0] = iv.x; inv[1] = iv.y; inv[2] = iv.z; inv[3] = iv.w;
    }
    float mul = (mode == 0) ? (1.0f / 32.0f) : 1.0f;
    float sc[4];
#pragma unroll
    for (int j = 0; j < 4; j++) sc[j] = inv[j] * mul;

    int sbase = bc * NP * HW + q4 * 4;
    float sv[NP][4];
    float n2[4] = {EPSF, EPSF, EPSF, EPSF};
#pragma unroll
    for (int p = 0; p < NP; p++) {
        float4 x = *(const float4*)&g_s[sbase + p * HW];
        float xs[4] = {x.x * sc[0], x.y * sc[1], x.z * sc[2], x.w * sc[3]};
#pragma unroll
        for (int j = 0; j < 4; j++) { sv[p][j] = xs[j]; n2[j] += xs[j] * xs[j]; }
    }
    float f[4];
#pragma unroll
    for (int j = 0; j < 4; j++) f[j] = 1.0f / (1.0f + sqrtf(n2[j]));

    if (mode < 2) {
#pragma unroll
        for (int p = 0; p < NP; p++) {
            float4 vold = make_float4(0.f, 0.f, 0.f, 0.f);
            if (mode == 1) vold = *(const float4*)&g_v[sbase + p * HW];
            float4 vn;
            vn.x = vold.x + sv[p][0] * f[0];
            vn.y = vold.y + sv[p][1] * f[1];
            vn.z = vold.z + sv[p][2] * f[2];
            vn.w = vold.w + sv[p][3] * f[3];
            *(float4*)&g_v[sbase + p * HW] = vn;
            *(float4*)&g_s[sbase + p * HW] = make_float4(0.f, 0.f, 0.f, 0.f);
        }
    } else {
        float av2[4] = {EPSF, EPSF, EPSF, EPSF};
#pragma unroll
        for (int p = 0; p < NP; p++) {
            float4 vn;
            vn.x = sv[p][0] * f[0]; vn.y = sv[p][1] * f[1];
            vn.z = sv[p][2] * f[2]; vn.w = sv[p][3] * f[3];
            *(float4*)&vout[sbase + p * HW] = vn;
            av2[0] += vn.x * vn.x; av2[1] += vn.y * vn.y;
            av2[2] += vn.z * vn.z; av2[3] += vn.w * vn.w;
        }
#pragma unroll
        for (int j = 0; j < 4; j++) aout[mi + j] = sqrtf(av2[j]);
    }
}

// ---------------------------------------------------------------------------
// Routing pass v14: reads the fp16 repack, FULLY COALESCED (warp lanes =
// consecutive uint2 = 256B/warp-LDG, 2 wavefronts @128B). Block covers 28 hw
// (4 per thread). grid (9, 7, 4) = 252, 224 thr, 2 blocks/SM -> ONE wave.
// v (fp32) in dynamic smem per-thread slots; acc fp32 in registers.
#define RTH 224
extern __shared__ float smdyn[];

__global__ void __launch_bounds__(RTH, 2) k_route() {
    float4* v_sh    = (float4*)smdyn;             // 16*224 float4 = 57344 B
    float*  e_sh    = smdyn + 4 * NP * RTH;       // [32][36] = 4608 B
    float*  dinv_sh = e_sh + NC * 36;             // 32 floats

    int bg = blockIdx.x;   // 0..8
    int hq = blockIdx.y;   // 0..6
    int b  = blockIdx.z;   // 0..3
    int tid = threadIdx.x;
    int c  = tid / 7;             // 0..31
    int q4 = tid % 7;             // 0..6
    int hwoff = hq * 28 + q4 * 4;

    // v (bi-invariant) into per-thread smem slots; inv into registers
    const float* vb = g_v + ((size_t)(b * NC + c) * NP) * HW + hwoff;
#pragma unroll
    for (int p = 0; p < NP; p++) v_sh[p * RTH + tid] = *(const float4*)(vb + p * HW);
    float4 invv = *(const float4*)&g_inv[(b * NC + c) * HW + hwoff];
    __syncthreads();

    float4 acc[NP];
#pragma unroll
    for (int p = 0; p < NP; p++) acc[p] = make_float4(0.f, 0.f, 0.f, 0.f);

    const uint2* ubase = g_u16 + (((size_t)(b * NB + bg * 32) * 7 + hq) * NP) * 224 + tid;
    const size_t ustep = (size_t)7 * NP * 224;   // 25088 uint2 per B

    for (int bi = 0; bi < 32; bi++) {
        const uint2* up = ubase + (size_t)bi * ustep;
        uint2 u16[NP];
#pragma unroll
        for (int p = 0; p < NP; p++) u16[p] = up[p * 224];   // coalesced LDG.64

        // agreement r = sum_P u.v  (convert on the fly)
        float4 r = make_float4(0.f, 0.f, 0.f, 0.f);
#pragma unroll
        for (int p = 0; p < NP; p++) {
            float4 vv = v_sh[p * RTH + tid];
            float2 lo = __half22float2(*(__half2*)&u16[p].x);
            float2 hi = __half22float2(*(__half2*)&u16[p].y);
            r.x += lo.x * vv.x; r.y += lo.y * vv.y;
            r.z += hi.x * vv.z; r.w += hi.y * vv.w;
        }
        // softmax numerator (|r*inv| small: safe without max subtraction)
        float4 e;
        e.x = __expf(r.x * invv.x); e.y = __expf(r.y * invv.y);
        e.z = __expf(r.z * invv.z); e.w = __expf(r.w * invv.w);
        *(float4*)&e_sh[c * 36 + q4 * 4] = e;
        __syncthreads();

        if (tid < 28) {
            float s = 0.f;
#pragma unroll
            for (int cc = 0; cc < NC; cc++) s += e_sh[cc * 36 + tid];
            dinv_sh[tid] = __frcp_rn(s);
        }
        __syncthreads();

        float4 d = *(const float4*)&dinv_sh[q4 * 4];
        float4 cv;
        cv.x = e.x * d.x; cv.y = e.y * d.y;
        cv.z = e.z * d.z; cv.w = e.w * d.w;

        // s += c * u  (reconvert held fp16 regs — cheap ALU, no reload)
#pragma unroll
        for (int p = 0; p < NP; p++) {
            float2 lo = __half22float2(*(__half2*)&u16[p].x);
            float2 hi = __half22float2(*(__half2*)&u16[p].y);
            acc[p].x += cv.x * lo.x; acc[p].y += cv.y * lo.y;
            acc[p].z += cv.z * hi.x; acc[p].w += cv.w * hi.y;
        }
    }

    int sbase = ((b * NC + c) * NP) * HW + hwoff;
#pragma unroll
    for (int p = 0; p < NP; p++) {
        atomicAdd(&g_s[sbase + p * HW + 0], acc[p].x);
        atomicAdd(&g_s[sbase + p * HW + 1], acc[p].y);
        atomicAdd(&g_s[sbase + p * HW + 2], acc[p].z);
        atomicAdd(&g_s[sbase + p * HW + 3], acc[p].w);
    }
}

// ---------------------------------------------------------------------------
extern "C" void kernel_launch(void* const* d_in, const int* in_sizes, int n_in,
                              void* d_out, int out_size) {
    const float* u = (const float*)d_in[0];   // (4,288,32,16,14,14)
    float* out  = (float*)d_out;
    float* vout = out;                        // (4,32,16,14,14)
    float* aout = out + NVPHW;                // (4,32,14,14)

    const int shbytes = (4 * NP * RTH + NC * 36 + 32) * sizeof(float); // 62,080 B
    cudaFuncSetAttribute(k_route, cudaFuncAttributeMaxDynamicSharedMemorySize, shbytes);

    k_init<<<(NVPHW + 255) / 256, 256>>>();
    k_passA<<<dim3(9, 4, 4), 392>>>(u);
    k_squash<<<(NCHW4 + 255) / 256, 256>>>(nullptr, nullptr, 0);  // v0 = squash(s0)
    k_route<<<dim3(9, 7, 4), RTH, shbytes>>>();                   // s1 (uses v0)
    k_squash<<<(NCHW4 + 255) / 256, 256>>>(nullptr, nullptr, 1);  // g_v = v0+v1
    k_route<<<dim3(9, 7, 4), RTH, shbytes>>>();                   // s2 (uses v0+v1)
    k_squash<<<(NCHW4 + 255) / 256, 256>>>(vout, aout, 2);        // v2, a_out
}